// round 14
// baseline (speedup 1.0000x reference)
#include <cuda_runtime.h>
#include <cuda_fp16.h>
#include <cstdint>

// InstantNGP 2D hash-grid bilinear lookup — two-pass de-hash, fp16 records.
//
// Pass 1 (dehash): each thread builds TWO cell records (even c0 base) using
// the XOR pair-merge: for even c0, table entries c0^h and (c0+1)^h form one
// aligned float4 => 2xLDG.128 + 2xLDG.64 per 2 cells (was 8xLDG.64).
// Pass 2 (lookup, R11 shape — confirmed local optimum): 2 points/thread,
// 128-thread blocks, __ldcs coord reads, __stcs out writes, one scattered
// LDG.128 per point into the L2-resident 16.8MB H table.

#define TABLE_MASK 524287u
#define PI2 2654435761u
#define GRID 1024

// 1024*1024 cells * 16B = 16.8 MB scratch.
__device__ uint4 g_H[GRID * GRID];

__device__ __forceinline__ float2 sel_half(float4 v, unsigned bit) {
    return bit ? make_float2(v.z, v.w) : make_float2(v.x, v.y);
}

__device__ __forceinline__ unsigned pack_h2(float2 f) {
    half2 h = __float22half2_rn(f);
    return *reinterpret_cast<unsigned*>(&h);
}

__global__ __launch_bounds__(256)
void dehash_kernel(const float2* __restrict__ table,
                   const float4* __restrict__ table4)
{
    int t = blockIdx.x * blockDim.x + threadIdx.x;   // 0 .. GRID*GRID/2 - 1
    unsigned c0 = (unsigned)((t & (GRID / 2 - 1)) << 1);  // even
    unsigned c1 = (unsigned)(t >> 9);

    unsigned ha = c1 * PI2;
    unsigned hb = ha + PI2;

    unsigned ia = (c0 ^ ha) & TABLE_MASK;   // even c0: pairs with (c0+1)^ha = ia^1
    unsigned ib = (c0 ^ hb) & TABLE_MASK;
    unsigned ka = ((c0 + 2u) ^ ha) & TABLE_MASK;  // corner c0+2
    unsigned kb = ((c0 + 2u) ^ hb) & TABLE_MASK;

    float4 A = __ldg(&table4[ia >> 1]);     // corners {c0, c0+1} row a
    float4 B = __ldg(&table4[ib >> 1]);     // corners {c0, c0+1} row b
    float2 fa2 = __ldg(&table[ka]);         // corner c0+2 row a
    float2 fb2 = __ldg(&table[kb]);         // corner c0+2 row b

    float2 fa0 = sel_half(A, ia & 1u);          // (c0,   c1)
    float2 fa1 = sel_half(A, (ia & 1u) ^ 1u);   // (c0+1, c1)
    float2 fb0 = sel_half(B, ib & 1u);          // (c0,   c1+1)
    float2 fb1 = sel_half(B, (ib & 1u) ^ 1u);   // (c0+1, c1+1)

    unsigned cell = (c1 << 10) | c0;

    uint4 r0;   // cell (c0, c1): corners c0, c0+1
    r0.x = pack_h2(fa0);
    r0.y = pack_h2(fa1);
    r0.z = pack_h2(fb0);
    r0.w = pack_h2(fb1);

    uint4 r1;   // cell (c0+1, c1): corners c0+1, c0+2
    r1.x = pack_h2(fa1);
    r1.y = pack_h2(fa2);
    r1.z = pack_h2(fb1);
    r1.w = pack_h2(fb2);

    g_H[cell]      = r0;
    g_H[cell + 1u] = r1;
}

__global__ __launch_bounds__(128)
void lookup_kernel(const float4* __restrict__ x4,
                   float4* __restrict__ out4,
                   int npack)   // npack = n/2 (2 points per thread)
{
    int i = blockIdx.x * blockDim.x + threadIdx.x;
    if (i >= npack) return;

    float4 p = __ldcs(&x4[i]);   // streaming read
    float px[2] = {p.x, p.z};
    float py[2] = {p.y, p.w};

    float fx[2], fy[2];
    unsigned cell[2];

    #pragma unroll
    for (int j = 0; j < 2; j++) {
        float xs = px[j] * 1024.0f;
        float ys = py[j] * 1024.0f;
        float fx0 = floorf(xs);
        float fy0 = floorf(ys);
        fx[j] = xs - fx0;
        fy[j] = ys - fy0;
        cell[j] = (((unsigned)fy0) << 10) | (unsigned)fx0;
    }

    uint4 rec[2];
    rec[0] = __ldg(&g_H[cell[0]]);
    rec[1] = __ldg(&g_H[cell[1]]);

    float o[4];
    #pragma unroll
    for (int j = 0; j < 2; j++) {
        float2 f00 = __half22float2(*reinterpret_cast<half2*>(&rec[j].x));
        float2 f10 = __half22float2(*reinterpret_cast<half2*>(&rec[j].y));
        float2 f01 = __half22float2(*reinterpret_cast<half2*>(&rec[j].z));
        float2 f11 = __half22float2(*reinterpret_cast<half2*>(&rec[j].w));

        float gx = 1.0f - fx[j];
        float gy = 1.0f - fy[j];
        float w00 = gx * gy;
        float w10 = fx[j] * gy;
        float w01 = gx * fy[j];
        float w11 = fx[j] * fy[j];

        o[2 * j + 0] = f00.x * w00 + f10.x * w10 + f01.x * w01 + f11.x * w11;
        o[2 * j + 1] = f00.y * w00 + f10.y * w10 + f01.y * w01 + f11.y * w11;
    }

    __stcs(&out4[i], make_float4(o[0], o[1], o[2], o[3]));
}

extern "C" void kernel_launch(void* const* d_in, const int* in_sizes, int n_in,
                              void* d_out, int out_size)
{
    const float4* x4     = (const float4*)d_in[0];   // [B,2] f32 as float4
    const float2* table  = (const float2*)d_in[1];   // [524288,2] f32
    const float4* table4 = (const float4*)d_in[1];
    float4* out4         = (float4*)d_out;

    int n = in_sizes[0] / 2;   // number of points (4194304, divisible by 2)
    int npack = n / 2;

    int threads_dehash = GRID * GRID / 2;   // 2 cells per thread
    dehash_kernel<<<threads_dehash / 256, 256>>>(table, table4);
    lookup_kernel<<<(npack + 127) / 128, 128>>>(x4, out4, npack);
}

// round 15
// speedup vs baseline: 1.0618x; 1.0618x over previous
#include <cuda_runtime.h>
#include <cuda_fp16.h>
#include <cstdint>

// InstantNGP 2D hash-grid bilinear lookup — two-pass de-hash, fp16 records.
//
// Pass 1 (dehash): 1 cell/thread (1M threads — uniform lightweight shape that
// benches best). Within a warp, lane i+1's corner (c0+1,c1) equals lane i's
// f10, so f10/f11 come from __shfl_down of the neighbor's f00/f01; only lane
// 31 loads them directly. Gather loads per cell: 4 -> ~2.06.
// Pass 2 (lookup, R11 shape — confirmed optimum): 2 points/thread, 128-thread
// blocks, __ldcs coord reads, __stcs out writes, one scattered LDG.128 per
// point into the L2-resident 16.8MB H table.

#define TABLE_MASK 524287u
#define PI2 2654435761u
#define GRID 1024

// 1024*1024 cells * 16B = 16.8 MB scratch.
__device__ uint4 g_H[GRID * GRID];

__device__ __forceinline__ unsigned hashidx(unsigned c0, unsigned c1) {
    return (c0 ^ (c1 * PI2)) & TABLE_MASK;
}

__device__ __forceinline__ unsigned pack_h2(float2 f) {
    half2 h = __float22half2_rn(f);
    return *reinterpret_cast<unsigned*>(&h);
}

__global__ __launch_bounds__(256)
void dehash_kernel(const float2* __restrict__ table)
{
    int i = blockIdx.x * blockDim.x + threadIdx.x;   // cell id
    unsigned c0 = (unsigned)(i & (GRID - 1));
    unsigned c1 = (unsigned)(i >> 10);
    unsigned lane = (unsigned)(threadIdx.x & 31);

    // Each lane loads its own (c0, c1) and (c0, c1+1) corners — coalesced.
    float2 f00 = __ldg(&table[hashidx(c0, c1)]);
    float2 f01 = __ldg(&table[hashidx(c0, c1 + 1u)]);

    // Neighbor lane's f00/f01 are this lane's f10/f11 (consecutive c0 in-warp;
    // warps never straddle a grid row since 1024 % 32 == 0).
    float2 f10, f11;
    f10.x = __shfl_down_sync(0xFFFFFFFFu, f00.x, 1);
    f10.y = __shfl_down_sync(0xFFFFFFFFu, f00.y, 1);
    f11.x = __shfl_down_sync(0xFFFFFFFFu, f01.x, 1);
    f11.y = __shfl_down_sync(0xFFFFFFFFu, f01.y, 1);
    if (lane == 31u) {
        f10 = __ldg(&table[hashidx(c0 + 1u, c1)]);
        f11 = __ldg(&table[hashidx(c0 + 1u, c1 + 1u)]);
    }

    uint4 rec;
    rec.x = pack_h2(f00);
    rec.y = pack_h2(f10);
    rec.z = pack_h2(f01);
    rec.w = pack_h2(f11);
    g_H[i] = rec;
}

__global__ __launch_bounds__(128)
void lookup_kernel(const float4* __restrict__ x4,
                   float4* __restrict__ out4,
                   int npack)   // npack = n/2 (2 points per thread)
{
    int i = blockIdx.x * blockDim.x + threadIdx.x;
    if (i >= npack) return;

    float4 p = __ldcs(&x4[i]);   // streaming read
    float px[2] = {p.x, p.z};
    float py[2] = {p.y, p.w};

    float fx[2], fy[2];
    unsigned cell[2];

    #pragma unroll
    for (int j = 0; j < 2; j++) {
        float xs = px[j] * 1024.0f;
        float ys = py[j] * 1024.0f;
        float fx0 = floorf(xs);
        float fy0 = floorf(ys);
        fx[j] = xs - fx0;
        fy[j] = ys - fy0;
        cell[j] = (((unsigned)fy0) << 10) | (unsigned)fx0;
    }

    // 2 independent scattered LDG.128 (H stays L2-hot).
    uint4 rec[2];
    rec[0] = __ldg(&g_H[cell[0]]);
    rec[1] = __ldg(&g_H[cell[1]]);

    float o[4];
    #pragma unroll
    for (int j = 0; j < 2; j++) {
        float2 f00 = __half22float2(*reinterpret_cast<half2*>(&rec[j].x));
        float2 f10 = __half22float2(*reinterpret_cast<half2*>(&rec[j].y));
        float2 f01 = __half22float2(*reinterpret_cast<half2*>(&rec[j].z));
        float2 f11 = __half22float2(*reinterpret_cast<half2*>(&rec[j].w));

        float gx = 1.0f - fx[j];
        float gy = 1.0f - fy[j];
        float w00 = gx * gy;
        float w10 = fx[j] * gy;
        float w01 = gx * fy[j];
        float w11 = fx[j] * fy[j];

        o[2 * j + 0] = f00.x * w00 + f10.x * w10 + f01.x * w01 + f11.x * w11;
        o[2 * j + 1] = f00.y * w00 + f10.y * w10 + f01.y * w01 + f11.y * w11;
    }

    __stcs(&out4[i], make_float4(o[0], o[1], o[2], o[3]));  // streaming write
}

extern "C" void kernel_launch(void* const* d_in, const int* in_sizes, int n_in,
                              void* d_out, int out_size)
{
    const float4* x4    = (const float4*)d_in[0];   // [B,2] f32 as float4
    const float2* table = (const float2*)d_in[1];   // [524288,2] f32
    float4* out4        = (float4*)d_out;

    int n = in_sizes[0] / 2;   // number of points (4194304, divisible by 2)
    int npack = n / 2;

    int cells = GRID * GRID;
    dehash_kernel<<<cells / 256, 256>>>(table);
    lookup_kernel<<<(npack + 127) / 128, 128>>>(x4, out4, npack);
}